// round 14
// baseline (speedup 1.0000x reference)
#include <cuda_runtime.h>
#include <cuda_bf16.h>
#include <cstdint>

// ---------------- constants ----------------
#define SH    328          // smem row stride (elems) for H1/H2 tiles (conflict-free)
#define BM    64           // edges per block
#define NTHR  320          // 10 warps
// K padded to 304 = 19 k-steps of 16 (real K = 300)

// ---------------- device scratch: weights pre-swizzled into mma fragment order ----
// uint2 fragment = 32 lanes x {b0,b1}: b0={W[k0][n],W[k0+1][n]}, b1={W[k0+8..9][n]}
// n = base_n + lane/4, k0 = base_k + (lane%4)*2   (m16n8k16.row.col B layout)
// uint4 pair = fragments for k-steps (2*ksp, 2*ksp+1): {x,y}=even step, {z,w}=odd step
__device__ uint2 g_W1f[40 * 32];       // (cg10, ni4): f = cg*4 + ni
__device__ uint4 g_W2q[400 * 32];      // (cg10, ni4, ksp10): f = cg*40 + ni*10 + ksp
__device__ uint4 g_W3q[250 * 32];      // (cg5,  ni5, ksp10): f = cg*50 + ni*10 + ksp
__device__ double g_acc[2];            // [0]=sum|y-t|, [1]=KL

__device__ __forceinline__ uint32_t smem_u32(const void* p) {
    return (uint32_t)__cvta_generic_to_shared(p);
}

#define PF_L1(p) asm volatile("prefetch.global.L1 [%0];" :: "l"(p))

__device__ __forceinline__ uint32_t pk2(const float* W, int k, int n,
                                        int K, int N, int ld) {
    float v0 = (k     < K && n < N) ? W[(size_t)k * ld + n]       : 0.f;
    float v1 = (k + 1 < K && n < N) ? W[(size_t)(k + 1) * ld + n] : 0.f;
    __nv_bfloat162 h = __floats2bfloat162_rn(v0, v1);
    return *(uint32_t*)&h;
}

__global__ void k_zero() { g_acc[0] = 0.0; g_acc[1] = 0.0; }

__global__ void k_base(const float* __restrict__ y, const float* __restrict__ tg, int n) {
    __shared__ float red[8];
    float local = 0.f;
    for (int i = blockIdx.x * blockDim.x + threadIdx.x; i < n; i += gridDim.x * blockDim.x)
        local += fabsf(y[i] - tg[i]);
    int lane = threadIdx.x & 31, warp = threadIdx.x >> 5;
    #pragma unroll
    for (int o = 16; o > 0; o >>= 1) local += __shfl_xor_sync(0xffffffffu, local, o);
    if (lane == 0) red[warp] = local;
    __syncthreads();
    if (threadIdx.x < 8) {
        float v = red[threadIdx.x];
        #pragma unroll
        for (int o = 4; o > 0; o >>= 1) v += __shfl_xor_sync(0xffu, v, o);
        if (threadIdx.x == 0) atomicAdd(&g_acc[0], (double)v);
    }
}

// ---------------- fragment prep ----------------
__global__ void k_prep(const float* __restrict__ W1,
                       const float* __restrict__ W2,
                       const float* __restrict__ W3) {
    int i = blockIdx.x * blockDim.x + threadIdx.x;
    int lane = i & 31, f = i >> 5;
    if (i < 12800) {            // W2q: [300][300], ld=300
        int cg = f / 40, r = f % 40;
        int ni = r / 10, ksp = r % 10;
        int n  = cg * 32 + ni * 8 + (lane >> 2);
        int k0 = ksp * 32 + (lane & 3) * 2;      // even step base = 2*ksp*16
        g_W2q[i] = make_uint4(pk2(W2, k0,      n, 300, 300, 300),
                              pk2(W2, k0 + 8,  n, 300, 300, 300),
                              pk2(W2, k0 + 16, n, 300, 300, 300),
                              pk2(W2, k0 + 24, n, 300, 300, 300));
    }
    if (i < 8000) {             // W3q: [300][200], ld=200
        int cg = f / 50, r = f % 50;
        int ni = r / 10, ksp = r % 10;
        int n  = cg * 40 + ni * 8 + (lane >> 2);
        int k0 = ksp * 32 + (lane & 3) * 2;
        g_W3q[i] = make_uint4(pk2(W3, k0,      n, 300, 200, 200),
                              pk2(W3, k0 + 8,  n, 300, 200, 200),
                              pk2(W3, k0 + 16, n, 300, 200, 200),
                              pk2(W3, k0 + 24, n, 300, 200, 200));
    }
    if (i < 1280) {             // W1: [12][300], ld=300, K=16 single step
        int cg = f >> 2, ni = f & 3;
        int n  = cg * 32 + ni * 8 + (lane >> 2);
        int k0 = (lane & 3) * 2;
        g_W1f[i] = make_uint2(pk2(W1, k0,     n, 12, 300, 300),
                              pk2(W1, k0 + 8, n, 12, 300, 300));
    }
}

// ---------------- smem: H1 + H2 + Es + red = ~86 KB, 2 CTAs/SM ----------------
#define ELEMS (2 * 64 * SH + 64 * 16)
#define SMEM_BYTES (ELEMS * 2 + 64)

#define MMA(acc, a, bx, by) \
    asm volatile("mma.sync.aligned.m16n8k16.row.col.f32.bf16.bf16.f32 " \
        "{%0,%1,%2,%3}, {%4,%5,%6,%7}, {%8,%9}, {%0,%1,%2,%3};\n" \
        : "+f"(acc[0]), "+f"(acc[1]), "+f"(acc[2]), "+f"(acc[3]) \
        : "r"(a[0]), "r"(a[1]), "r"(a[2]), "r"(a[3]), "r"(bx), "r"(by))

__global__ __launch_bounds__(NTHR, 2)
void k_fused(const float* __restrict__ x,
             const int*   __restrict__ ei,
             const float* __restrict__ b1,
             const float* __restrict__ b2,
             const float* __restrict__ b3,
             int nEdges) {
    extern __shared__ __align__(16) char smem_raw[];
    __nv_bfloat16* base = (__nv_bfloat16*)smem_raw;
    __nv_bfloat16* H1 = base;
    __nv_bfloat16* H2 = base + 64 * SH;
    __nv_bfloat16* Es = base + 2 * 64 * SH;
    float* red = (float*)(base + ELEMS);

    const int t = threadIdx.x;
    const int lane = t & 31, warp = t >> 5;    // 10 warps
    const int mg = warp / 5;                   // m-half (stage 1/3)
    const int ig = warp % 5;                   // item group (stage 1/3)
    const int mBase = blockIdx.x * BM;
    const int g = lane >> 2, q = lane & 3;

    // per-warp B fragment streams
    const uint4* Bq2 = g_W2q + (size_t)warp * 40 * 32 + lane;   // GEMM2: item = warp
    const uint4* Bq3 = g_W3q + (size_t)ig * 50 * 32 + lane;     // GEMM3: item = ig

    // ---- stage 0: edge gather into Es (+ prefetch GEMM2 first k-iter B) ----
    #pragma unroll
    for (int ni = 0; ni < 4; ni++) PF_L1(Bq2 + (ni * 10) * 32);
    if (t < 128) {
        int el = t >> 1, half = t & 1;
        int e = mBase + el;
        __nv_bfloat16* row = Es + el * 16 + half * 6;
        float v[6] = {0.f, 0.f, 0.f, 0.f, 0.f, 0.f};
        if (e < nEdges) {
            int node = ei[half ? (size_t)nEdges + e : (size_t)e];
            const float* xp = x + (size_t)node * 6;
            float2 a0 = *(const float2*)xp;
            float2 a1 = *(const float2*)(xp + 2);
            float2 a2 = *(const float2*)(xp + 4);
            v[0] = a0.x; v[1] = a0.y; v[2] = a1.x; v[3] = a1.y; v[4] = a2.x; v[5] = a2.y;
        }
        #pragma unroll
        for (int k = 0; k < 6; k++) row[k] = __float2bfloat16(v[k]);
        if (half) {
            *(__nv_bfloat162*)(Es + el * 16 + 12) = __floats2bfloat162_rn(0.f, 0.f);
            *(__nv_bfloat162*)(Es + el * 16 + 14) = __floats2bfloat162_rn(0.f, 0.f);
        }
    }
    __syncthreads();

    // ---- stage 1: GEMM1 (Es @ W1) -> H1 ; 2mg x 5ig, items cg = ig, ig+5 ----
    {
        float acc[2][4][4];
        uint32_t a[2][4];
        const int arow = mg * 32 + (lane & 15);
        const int acol = (lane >> 4) * 8;
        #pragma unroll
        for (int mi = 0; mi < 2; mi++)
            asm volatile("ldmatrix.sync.aligned.m8n8.x4.shared.b16 {%0,%1,%2,%3}, [%4];\n"
                : "=r"(a[mi][0]), "=r"(a[mi][1]), "=r"(a[mi][2]), "=r"(a[mi][3])
                : "r"(smem_u32(Es + (arow + mi * 16) * 16 + acol)));
        #pragma unroll
        for (int it = 0; it < 2; it++) {
            const int cg = ig + it * 5;
            #pragma unroll
            for (int mi = 0; mi < 2; mi++)
                #pragma unroll
                for (int ni = 0; ni < 4; ni++)
                    #pragma unroll
                    for (int r = 0; r < 4; r++) acc[mi][ni][r] = 0.f;
            const uint2* Bf = g_W1f + (size_t)cg * 4 * 32 + lane;
            #pragma unroll
            for (int ni = 0; ni < 4; ni++) {
                uint2 bv = __ldg(Bf + ni * 32);
                #pragma unroll
                for (int mi = 0; mi < 2; mi++) MMA(acc[mi][ni], a[mi], bv.x, bv.y);
            }
            #pragma unroll
            for (int mi = 0; mi < 2; mi++)
                #pragma unroll
                for (int ni = 0; ni < 4; ni++) {
                    int c0 = cg * 32 + ni * 8 + q * 2;
                    float bb0 = (c0 < 300)     ? __ldg(b1 + c0)     : 0.f;
                    float bb1 = (c0 + 1 < 300) ? __ldg(b1 + c0 + 1) : 0.f;
                    int r0 = mg * 32 + mi * 16 + g;
                    *(__nv_bfloat162*)(H1 + r0 * SH + c0) = __floats2bfloat162_rn(
                        fmaxf(acc[mi][ni][0] + bb0, 0.f), fmaxf(acc[mi][ni][1] + bb1, 0.f));
                    *(__nv_bfloat162*)(H1 + (r0 + 8) * SH + c0) = __floats2bfloat162_rn(
                        fmaxf(acc[mi][ni][2] + bb0, 0.f), fmaxf(acc[mi][ni][3] + bb1, 0.f));
                }
        }
    }
    __syncthreads();   // H1 published

    // ---- stage 2: GEMM2 (H1 @ W2) -> H2 ; one item/warp, mi=4, NI=4, K=304 ----
    {
        float acc[4][4][4];
        #pragma unroll
        for (int mi = 0; mi < 4; mi++)
            #pragma unroll
            for (int ni = 0; ni < 4; ni++)
                #pragma unroll
                for (int r = 0; r < 4; r++) acc[mi][ni][r] = 0.f;
        const uint32_t aBase1 = smem_u32(H1 + (lane & 15) * SH) + ((lane >> 4) * 8) * 2;
        #pragma unroll
        for (int ksp = 0; ksp < 10; ksp++) {
            uint4 bq[4];
            #pragma unroll
            for (int ni = 0; ni < 4; ni++)
                bq[ni] = __ldg(Bq2 + (ni * 10 + ksp) * 32);
            // prefetch next k-iteration's B into L1 (harmless re-fetch at ksp=9)
            {
                int pk = (ksp < 9) ? ksp + 1 : 9;
                #pragma unroll
                for (int ni = 0; ni < 4; ni++) PF_L1(Bq2 + (ni * 10 + pk) * 32);
            }
            {   // even k-step (2*ksp)
                uint32_t a[4][4];
                const uint32_t ac = aBase1 + (ksp * 32) * 2;
                #pragma unroll
                for (int mi = 0; mi < 4; mi++)
                    asm volatile("ldmatrix.sync.aligned.m8n8.x4.shared.b16 {%0,%1,%2,%3}, [%4];\n"
                        : "=r"(a[mi][0]), "=r"(a[mi][1]), "=r"(a[mi][2]), "=r"(a[mi][3])
                        : "r"(ac + mi * 16 * SH * 2));
                #pragma unroll
                for (int mi = 0; mi < 4; mi++)
                    #pragma unroll
                    for (int ni = 0; ni < 4; ni++)
                        MMA(acc[mi][ni], a[mi], bq[ni].x, bq[ni].y);
            }
            if (ksp < 9) {   // odd k-step (2*ksp+1); step 19 doesn't exist (K=304)
                uint32_t a[4][4];
                const uint32_t ac = aBase1 + (ksp * 32 + 16) * 2;
                #pragma unroll
                for (int mi = 0; mi < 4; mi++)
                    asm volatile("ldmatrix.sync.aligned.m8n8.x4.shared.b16 {%0,%1,%2,%3}, [%4];\n"
                        : "=r"(a[mi][0]), "=r"(a[mi][1]), "=r"(a[mi][2]), "=r"(a[mi][3])
                        : "r"(ac + mi * 16 * SH * 2));
                #pragma unroll
                for (int mi = 0; mi < 4; mi++)
                    #pragma unroll
                    for (int ni = 0; ni < 4; ni++)
                        MMA(acc[mi][ni], a[mi], bq[ni].z, bq[ni].w);
            }
        }
        // prefetch GEMM3 first k-iteration B while storing epilogue
        #pragma unroll
        for (int ni = 0; ni < 5; ni++) PF_L1(Bq3 + (ni * 10) * 32);
        #pragma unroll
        for (int mi = 0; mi < 4; mi++)
            #pragma unroll
            for (int ni = 0; ni < 4; ni++) {
                int c0 = warp * 32 + ni * 8 + q * 2;
                float bb0 = (c0 < 300)     ? __ldg(b2 + c0)     : 0.f;
                float bb1 = (c0 + 1 < 300) ? __ldg(b2 + c0 + 1) : 0.f;
                int r0 = mi * 16 + g;
                *(__nv_bfloat162*)(H2 + r0 * SH + c0) = __floats2bfloat162_rn(
                    fmaxf(acc[mi][ni][0] + bb0, 0.f), fmaxf(acc[mi][ni][1] + bb1, 0.f));
                *(__nv_bfloat162*)(H2 + (r0 + 8) * SH + c0) = __floats2bfloat162_rn(
                    fmaxf(acc[mi][ni][2] + bb0, 0.f), fmaxf(acc[mi][ni][3] + bb1, 0.f));
            }
    }
    __syncthreads();   // H2 published

    // ---- stage 3: GEMM3 (H2 @ W3), 2mg x 5ig, NI=5, K=304, fused KL ----
    float localKL = 0.f;
    {
        float acc[2][5][4];
        #pragma unroll
        for (int mi = 0; mi < 2; mi++)
            #pragma unroll
            for (int ni = 0; ni < 5; ni++)
                #pragma unroll
                for (int r = 0; r < 4; r++) acc[mi][ni][r] = 0.f;
        const uint32_t aBase2 = smem_u32(H2 + (mg * 32 + (lane & 15)) * SH) + ((lane >> 4) * 8) * 2;
        #pragma unroll
        for (int ksp = 0; ksp < 10; ksp++) {
            uint4 bq[5];
            #pragma unroll
            for (int ni = 0; ni < 5; ni++)
                bq[ni] = __ldg(Bq3 + (ni * 10 + ksp) * 32);
            {
                int pk = (ksp < 9) ? ksp + 1 : 9;
                #pragma unroll
                for (int ni = 0; ni < 5; ni++) PF_L1(Bq3 + (ni * 10 + pk) * 32);
            }
            {
                uint32_t a[2][4];
                const uint32_t ac = aBase2 + (ksp * 32) * 2;
                #pragma unroll
                for (int mi = 0; mi < 2; mi++)
                    asm volatile("ldmatrix.sync.aligned.m8n8.x4.shared.b16 {%0,%1,%2,%3}, [%4];\n"
                        : "=r"(a[mi][0]), "=r"(a[mi][1]), "=r"(a[mi][2]), "=r"(a[mi][3])
                        : "r"(ac + mi * 16 * SH * 2));
                #pragma unroll
                for (int mi = 0; mi < 2; mi++)
                    #pragma unroll
                    for (int ni = 0; ni < 5; ni++)
                        MMA(acc[mi][ni], a[mi], bq[ni].x, bq[ni].y);
            }
            if (ksp < 9) {
                uint32_t a[2][4];
                const uint32_t ac = aBase2 + (ksp * 32 + 16) * 2;
                #pragma unroll
                for (int mi = 0; mi < 2; mi++)
                    asm volatile("ldmatrix.sync.aligned.m8n8.x4.shared.b16 {%0,%1,%2,%3}, [%4];\n"
                        : "=r"(a[mi][0]), "=r"(a[mi][1]), "=r"(a[mi][2]), "=r"(a[mi][3])
                        : "r"(ac + mi * 16 * SH * 2));
                #pragma unroll
                for (int mi = 0; mi < 2; mi++)
                    #pragma unroll
                    for (int ni = 0; ni < 5; ni++)
                        MMA(acc[mi][ni], a[mi], bq[ni].z, bq[ni].w);
            }
        }
        #pragma unroll
        for (int mi = 0; mi < 2; mi++)
            #pragma unroll
            for (int ni = 0; ni < 5; ni++) {
                int c0 = ig * 40 + ni * 8 + q * 2;       // 0..199
                int r0 = mBase + mg * 32 + mi * 16 + g;
                float bb0 = __ldg(b3 + c0), bb1 = __ldg(b3 + c0 + 1);
                #pragma unroll
                for (int h = 0; h < 2; h++) {
                    if (r0 + h * 8 >= nEdges) continue;
                    float v0 = acc[mi][ni][h * 2]     + bb0;
                    float v1 = acc[mi][ni][h * 2 + 1] + bb1;
                    localKL += (c0 < 100) ? 0.5f * (v0 * v0 + v1 * v1)
                                          : 0.5f * ((__expf(v0) - v0 - 1.f)
                                                  + (__expf(v1) - v1 - 1.f));
                }
            }
    }

    // ---- block reduce + atomic ----
    #pragma unroll
    for (int o = 16; o > 0; o >>= 1) localKL += __shfl_xor_sync(0xffffffffu, localKL, o);
    if (lane == 0) red[warp] = localKL;
    __syncthreads();
    if (t == 0) {
        float s = 0.f;
        #pragma unroll
        for (int w = 0; w < 10; w++) s += red[w];
        atomicAdd(&g_acc[1], (double)s);
    }
}

__global__ void k_finalize(float* out, int nNodes, int nEdges) {
    out[0] = (float)(g_acc[0] / (double)nNodes + g_acc[1] / (double)nEdges);
}

extern "C" void kernel_launch(void* const* d_in, const int* in_sizes, int n_in,
                              void* d_out, int out_size) {
    const float* x   = (const float*)d_in[0];
    const int*   ei  = (const int*)  d_in[1];
    const float* y   = (const float*)d_in[2];
    const float* tgt = (const float*)d_in[3];
    const float* W1  = (const float*)d_in[4];
    const float* b1  = (const float*)d_in[5];
    const float* W2  = (const float*)d_in[6];
    const float* b2  = (const float*)d_in[7];
    const float* W3  = (const float*)d_in[8];
    const float* b3  = (const float*)d_in[9];
    float* out = (float*)d_out;

    const int nNodes = in_sizes[0] / 6;
    const int nEdges = in_sizes[1] / 2;
    const int nY     = in_sizes[2];

    cudaFuncSetAttribute(k_fused, cudaFuncAttributeMaxDynamicSharedMemorySize, SMEM_BYTES);

    k_zero<<<1, 1>>>();
    k_base<<<128, 256>>>(y, tgt, nY);
    k_prep<<<(12800 + 255) / 256, 256>>>(W1, W2, W3);
    k_fused<<<(nEdges + BM - 1) / BM, NTHR, SMEM_BYTES>>>(x, ei, b1, b2, b3, nEdges);
    k_finalize<<<1, 1>>>(out, nNodes, nEdges);
}

// round 15
// speedup vs baseline: 1.0295x; 1.0295x over previous
#include <cuda_runtime.h>
#include <cuda_bf16.h>
#include <cstdint>

// ---------------- constants ----------------
#define SH    312          // smem row stride (elems) for H1/H2 tiles
                           // 312*2 mod 128 = 112 -> 8-row ldmatrix sets conflict-free
#define BM    64           // edges per block
#define NTHR  320          // 10 warps
// K padded to 304 = 19 k-steps of 16 (real K = 300)

// ---------------- device scratch: weights pre-swizzled into mma fragment order ----
// uint2 fragment = 32 lanes x {b0,b1}: b0={W[k0][n],W[k0+1][n]}, b1={W[k0+8..9][n]}
// n = base_n + lane/4, k0 = base_k + (lane%4)*2   (m16n8k16.row.col B layout)
// uint4 pair = fragments for k-steps (2*ksp, 2*ksp+1): {x,y}=even step, {z,w}=odd step
__device__ uint2 g_W1f[40 * 32];       // (cg10, ni4): f = cg*4 + ni
__device__ uint4 g_W2q[400 * 32];      // (cg10, ni4, ksp10): f = cg*40 + ni*10 + ksp
__device__ uint4 g_W3q[250 * 32];      // (cg5,  ni5, ksp10): f = cg*50 + ni*10 + ksp
__device__ double g_acc[2];            // [0]=sum|y-t|, [1]=KL

__device__ __forceinline__ uint32_t smem_u32(const void* p) {
    return (uint32_t)__cvta_generic_to_shared(p);
}

__device__ __forceinline__ uint32_t pk2(const float* W, int k, int n,
                                        int K, int N, int ld) {
    float v0 = (k     < K && n < N) ? W[(size_t)k * ld + n]       : 0.f;
    float v1 = (k + 1 < K && n < N) ? W[(size_t)(k + 1) * ld + n] : 0.f;
    __nv_bfloat162 h = __floats2bfloat162_rn(v0, v1);
    return *(uint32_t*)&h;
}

__global__ void k_zero() { g_acc[0] = 0.0; g_acc[1] = 0.0; }

__global__ void k_base(const float* __restrict__ y, const float* __restrict__ tg, int n) {
    __shared__ float red[8];
    float local = 0.f;
    for (int i = blockIdx.x * blockDim.x + threadIdx.x; i < n; i += gridDim.x * blockDim.x)
        local += fabsf(y[i] - tg[i]);
    int lane = threadIdx.x & 31, warp = threadIdx.x >> 5;
    #pragma unroll
    for (int o = 16; o > 0; o >>= 1) local += __shfl_xor_sync(0xffffffffu, local, o);
    if (lane == 0) red[warp] = local;
    __syncthreads();
    if (threadIdx.x < 8) {
        float v = red[threadIdx.x];
        #pragma unroll
        for (int o = 4; o > 0; o >>= 1) v += __shfl_xor_sync(0xffu, v, o);
        if (threadIdx.x == 0) atomicAdd(&g_acc[0], (double)v);
    }
}

// ---------------- fragment prep ----------------
__global__ void k_prep(const float* __restrict__ W1,
                       const float* __restrict__ W2,
                       const float* __restrict__ W3) {
    int i = blockIdx.x * blockDim.x + threadIdx.x;
    int lane = i & 31, f = i >> 5;
    if (i < 12800) {            // W2q: [300][300], ld=300
        int cg = f / 40, r = f % 40;
        int ni = r / 10, ksp = r % 10;
        int n  = cg * 32 + ni * 8 + (lane >> 2);
        int k0 = ksp * 32 + (lane & 3) * 2;      // even step base = 2*ksp*16
        g_W2q[i] = make_uint4(pk2(W2, k0,      n, 300, 300, 300),
                              pk2(W2, k0 + 8,  n, 300, 300, 300),
                              pk2(W2, k0 + 16, n, 300, 300, 300),
                              pk2(W2, k0 + 24, n, 300, 300, 300));
    }
    if (i < 8000) {             // W3q: [300][200], ld=200
        int cg = f / 50, r = f % 50;
        int ni = r / 10, ksp = r % 10;
        int n  = cg * 40 + ni * 8 + (lane >> 2);
        int k0 = ksp * 32 + (lane & 3) * 2;
        g_W3q[i] = make_uint4(pk2(W3, k0,      n, 300, 200, 200),
                              pk2(W3, k0 + 8,  n, 300, 200, 200),
                              pk2(W3, k0 + 16, n, 300, 200, 200),
                              pk2(W3, k0 + 24, n, 300, 200, 200));
    }
    if (i < 1280) {             // W1: [12][300], ld=300, K=16 single step
        int cg = f >> 2, ni = f & 3;
        int n  = cg * 32 + ni * 8 + (lane >> 2);
        int k0 = (lane & 3) * 2;
        g_W1f[i] = make_uint2(pk2(W1, k0,     n, 12, 300, 300),
                              pk2(W1, k0 + 8, n, 12, 300, 300));
    }
}

// ---------------- smem: H1 + H2 + Es + red = ~82 KB, 2 CTAs/SM ----------------
#define ELEMS (2 * 64 * SH + 64 * 16)
#define SMEM_BYTES (ELEMS * 2 + 64)

#define MMA(acc, a, bx, by) \
    asm volatile("mma.sync.aligned.m16n8k16.row.col.f32.bf16.bf16.f32 " \
        "{%0,%1,%2,%3}, {%4,%5,%6,%7}, {%8,%9}, {%0,%1,%2,%3};\n" \
        : "+f"(acc[0]), "+f"(acc[1]), "+f"(acc[2]), "+f"(acc[3]) \
        : "r"(a[0]), "r"(a[1]), "r"(a[2]), "r"(a[3]), "r"(bx), "r"(by))

__global__ __launch_bounds__(NTHR, 2)
void k_fused(const float* __restrict__ x,
             const int*   __restrict__ ei,
             const float* __restrict__ b1,
             const float* __restrict__ b2,
             const float* __restrict__ b3,
             int nEdges) {
    extern __shared__ __align__(16) char smem_raw[];
    __nv_bfloat16* base = (__nv_bfloat16*)smem_raw;
    __nv_bfloat16* H1 = base;
    __nv_bfloat16* H2 = base + 64 * SH;
    __nv_bfloat16* Es = base + 2 * 64 * SH;
    float* red = (float*)(base + ELEMS);

    const int t = threadIdx.x;
    const int lane = t & 31, warp = t >> 5;    // 10 warps
    const int mg = warp / 5;                   // m-half (stage 1/3)
    const int ig = warp % 5;                   // item group (stage 1/3)
    const int mBase = blockIdx.x * BM;
    const int g = lane >> 2, q = lane & 3;

    // ---- stage 0: edge gather into Es ----
    if (t < 128) {
        int el = t >> 1, half = t & 1;
        int e = mBase + el;
        __nv_bfloat16* row = Es + el * 16 + half * 6;
        float v[6] = {0.f, 0.f, 0.f, 0.f, 0.f, 0.f};
        if (e < nEdges) {
            int node = ei[half ? (size_t)nEdges + e : (size_t)e];
            const float* xp = x + (size_t)node * 6;
            float2 a0 = *(const float2*)xp;
            float2 a1 = *(const float2*)(xp + 2);
            float2 a2 = *(const float2*)(xp + 4);
            v[0] = a0.x; v[1] = a0.y; v[2] = a1.x; v[3] = a1.y; v[4] = a2.x; v[5] = a2.y;
        }
        #pragma unroll
        for (int k = 0; k < 6; k++) row[k] = __float2bfloat16(v[k]);
        if (half) {
            *(__nv_bfloat162*)(Es + el * 16 + 12) = __floats2bfloat162_rn(0.f, 0.f);
            *(__nv_bfloat162*)(Es + el * 16 + 14) = __floats2bfloat162_rn(0.f, 0.f);
        }
    }
    __syncthreads();

    // ---- stage 1: GEMM1 (Es @ W1) -> H1 cols 0..303 ; items cg = ig, ig+5 ----
    {
        float acc[2][4][4];
        uint32_t a[2][4];
        const int arow = mg * 32 + (lane & 15);
        const int acol = (lane >> 4) * 8;
        #pragma unroll
        for (int mi = 0; mi < 2; mi++)
            asm volatile("ldmatrix.sync.aligned.m8n8.x4.shared.b16 {%0,%1,%2,%3}, [%4];\n"
                : "=r"(a[mi][0]), "=r"(a[mi][1]), "=r"(a[mi][2]), "=r"(a[mi][3])
                : "r"(smem_u32(Es + (arow + mi * 16) * 16 + acol)));
        #pragma unroll
        for (int it = 0; it < 2; it++) {
            const int cg = ig + it * 5;
            #pragma unroll
            for (int mi = 0; mi < 2; mi++)
                #pragma unroll
                for (int ni = 0; ni < 4; ni++)
                    #pragma unroll
                    for (int r = 0; r < 4; r++) acc[mi][ni][r] = 0.f;
            const uint2* Bf = g_W1f + (size_t)cg * 4 * 32 + lane;
            #pragma unroll
            for (int ni = 0; ni < 4; ni++) {
                uint2 bv = __ldg(Bf + ni * 32);
                #pragma unroll
                for (int mi = 0; mi < 2; mi++) MMA(acc[mi][ni], a[mi], bv.x, bv.y);
            }
            #pragma unroll
            for (int mi = 0; mi < 2; mi++)
                #pragma unroll
                for (int ni = 0; ni < 4; ni++) {
                    int c0 = cg * 32 + ni * 8 + q * 2;
                    if (c0 >= 304) continue;             // cols 304.. never read
                    float bb0 = (c0 < 300)     ? __ldg(b1 + c0)     : 0.f;
                    float bb1 = (c0 + 1 < 300) ? __ldg(b1 + c0 + 1) : 0.f;
                    int r0 = mg * 32 + mi * 16 + g;
                    *(__nv_bfloat162*)(H1 + r0 * SH + c0) = __floats2bfloat162_rn(
                        fmaxf(acc[mi][ni][0] + bb0, 0.f), fmaxf(acc[mi][ni][1] + bb1, 0.f));
                    *(__nv_bfloat162*)(H1 + (r0 + 8) * SH + c0) = __floats2bfloat162_rn(
                        fmaxf(acc[mi][ni][2] + bb0, 0.f), fmaxf(acc[mi][ni][3] + bb1, 0.f));
                }
        }
    }
    __syncthreads();   // H1 published

    // ---- stage 2: GEMM2 (H1 @ W2) -> H2 cols 0..303 ; one item/warp, mi=4, NI=4 ----
    // MMA work is fully uniform across warps; only stores are guarded at c0>=304.
    {
        float acc[4][4][4];
        const int cg = warp;
        #pragma unroll
        for (int mi = 0; mi < 4; mi++)
            #pragma unroll
            for (int ni = 0; ni < 4; ni++)
                #pragma unroll
                for (int r = 0; r < 4; r++) acc[mi][ni][r] = 0.f;
        const uint32_t aBase1 = smem_u32(H1 + (lane & 15) * SH) + ((lane >> 4) * 8) * 2;
        const uint4* Bq = g_W2q + (size_t)cg * 40 * 32 + lane;
        #pragma unroll
        for (int ksp = 0; ksp < 10; ksp++) {
            uint4 bq[4];
            #pragma unroll
            for (int ni = 0; ni < 4; ni++)
                bq[ni] = __ldg(Bq + (ni * 10 + ksp) * 32);
            {   // even k-step (2*ksp)
                uint32_t a[4][4];
                const uint32_t ac = aBase1 + (ksp * 32) * 2;
                #pragma unroll
                for (int mi = 0; mi < 4; mi++)
                    asm volatile("ldmatrix.sync.aligned.m8n8.x4.shared.b16 {%0,%1,%2,%3}, [%4];\n"
                        : "=r"(a[mi][0]), "=r"(a[mi][1]), "=r"(a[mi][2]), "=r"(a[mi][3])
                        : "r"(ac + mi * 16 * SH * 2));
                #pragma unroll
                for (int mi = 0; mi < 4; mi++)
                    #pragma unroll
                    for (int ni = 0; ni < 4; ni++)
                        MMA(acc[mi][ni], a[mi], bq[ni].x, bq[ni].y);
            }
            if (ksp < 9) {   // odd k-step (2*ksp+1); step 19 doesn't exist (K=304)
                uint32_t a[4][4];
                const uint32_t ac = aBase1 + (ksp * 32 + 16) * 2;
                #pragma unroll
                for (int mi = 0; mi < 4; mi++)
                    asm volatile("ldmatrix.sync.aligned.m8n8.x4.shared.b16 {%0,%1,%2,%3}, [%4];\n"
                        : "=r"(a[mi][0]), "=r"(a[mi][1]), "=r"(a[mi][2]), "=r"(a[mi][3])
                        : "r"(ac + mi * 16 * SH * 2));
                #pragma unroll
                for (int mi = 0; mi < 4; mi++)
                    #pragma unroll
                    for (int ni = 0; ni < 4; ni++)
                        MMA(acc[mi][ni], a[mi], bq[ni].z, bq[ni].w);
            }
        }
        #pragma unroll
        for (int mi = 0; mi < 4; mi++)
            #pragma unroll
            for (int ni = 0; ni < 4; ni++) {
                int c0 = cg * 32 + ni * 8 + q * 2;
                if (c0 >= 304) continue;                 // cols 304.. never read
                float bb0 = (c0 < 300)     ? __ldg(b2 + c0)     : 0.f;
                float bb1 = (c0 + 1 < 300) ? __ldg(b2 + c0 + 1) : 0.f;
                int r0 = mi * 16 + g;
                *(__nv_bfloat162*)(H2 + r0 * SH + c0) = __floats2bfloat162_rn(
                    fmaxf(acc[mi][ni][0] + bb0, 0.f), fmaxf(acc[mi][ni][1] + bb1, 0.f));
                *(__nv_bfloat162*)(H2 + (r0 + 8) * SH + c0) = __floats2bfloat162_rn(
                    fmaxf(acc[mi][ni][2] + bb0, 0.f), fmaxf(acc[mi][ni][3] + bb1, 0.f));
            }
    }
    __syncthreads();   // H2 published

    // ---- stage 3: GEMM3 (H2 @ W3), 2mg x 5ig, NI=5, K=304, fused KL ----
    float localKL = 0.f;
    {
        float acc[2][5][4];
        const int cg = ig;
        #pragma unroll
        for (int mi = 0; mi < 2; mi++)
            #pragma unroll
            for (int ni = 0; ni < 5; ni++)
                #pragma unroll
                for (int r = 0; r < 4; r++) acc[mi][ni][r] = 0.f;
        const uint32_t aBase2 = smem_u32(H2 + (mg * 32 + (lane & 15)) * SH) + ((lane >> 4) * 8) * 2;
        const uint4* Bq = g_W3q + (size_t)cg * 50 * 32 + lane;
        #pragma unroll
        for (int ksp = 0; ksp < 10; ksp++) {
            uint4 bq[5];
            #pragma unroll
            for (int ni = 0; ni < 5; ni++)
                bq[ni] = __ldg(Bq + (ni * 10 + ksp) * 32);
            {
                uint32_t a[2][4];
                const uint32_t ac = aBase2 + (ksp * 32) * 2;
                #pragma unroll
                for (int mi = 0; mi < 2; mi++)
                    asm volatile("ldmatrix.sync.aligned.m8n8.x4.shared.b16 {%0,%1,%2,%3}, [%4];\n"
                        : "=r"(a[mi][0]), "=r"(a[mi][1]), "=r"(a[mi][2]), "=r"(a[mi][3])
                        : "r"(ac + mi * 16 * SH * 2));
                #pragma unroll
                for (int mi = 0; mi < 2; mi++)
                    #pragma unroll
                    for (int ni = 0; ni < 5; ni++)
                        MMA(acc[mi][ni], a[mi], bq[ni].x, bq[ni].y);
            }
            if (ksp < 9) {
                uint32_t a[2][4];
                const uint32_t ac = aBase2 + (ksp * 32 + 16) * 2;
                #pragma unroll
                for (int mi = 0; mi < 2; mi++)
                    asm volatile("ldmatrix.sync.aligned.m8n8.x4.shared.b16 {%0,%1,%2,%3}, [%4];\n"
                        : "=r"(a[mi][0]), "=r"(a[mi][1]), "=r"(a[mi][2]), "=r"(a[mi][3])
                        : "r"(ac + mi * 16 * SH * 2));
                #pragma unroll
                for (int mi = 0; mi < 2; mi++)
                    #pragma unroll
                    for (int ni = 0; ni < 5; ni++)
                        MMA(acc[mi][ni], a[mi], bq[ni].z, bq[ni].w);
            }
        }
        #pragma unroll
        for (int mi = 0; mi < 2; mi++)
            #pragma unroll
            for (int ni = 0; ni < 5; ni++) {
                int c0 = cg * 40 + ni * 8 + q * 2;       // 0..199
                int r0 = mBase + mg * 32 + mi * 16 + g;
                float bb0 = __ldg(b3 + c0), bb1 = __ldg(b3 + c0 + 1);
                #pragma unroll
                for (int h = 0; h < 2; h++) {
                    if (r0 + h * 8 >= nEdges) continue;
                    float v0 = acc[mi][ni][h * 2]     + bb0;
                    float v1 = acc[mi][ni][h * 2 + 1] + bb1;
                    localKL += (c0 < 100) ? 0.5f * (v0 * v0 + v1 * v1)
                                          : 0.5f * ((__expf(v0) - v0 - 1.f)
                                                  + (__expf(v1) - v1 - 1.f));
                }
            }
    }

    // ---- block reduce + atomic ----
    #pragma unroll
    for (int o = 16; o > 0; o >>= 1) localKL += __shfl_xor_sync(0xffffffffu, localKL, o);
    if (lane == 0) red[warp] = localKL;
    __syncthreads();
    if (t == 0) {
        float s = 0.f;
        #pragma unroll
        for (int w = 0; w < 10; w++) s += red[w];
        atomicAdd(&g_acc[1], (double)s);
    }
}

__global__ void k_finalize(float* out, int nNodes, int nEdges) {
    out[0] = (float)(g_acc[0] / (double)nNodes + g_acc[1] / (double)nEdges);
}

extern "C" void kernel_launch(void* const* d_in, const int* in_sizes, int n_in,
                              void* d_out, int out_size) {
    const float* x   = (const float*)d_in[0];
    const int*   ei  = (const int*)  d_in[1];
    const float* y   = (const float*)d_in[2];
    const float* tgt = (const float*)d_in[3];
    const float* W1  = (const float*)d_in[4];
    const float* b1  = (const float*)d_in[5];
    const float* W2  = (const float*)d_in[6];
    const float* b2  = (const float*)d_in[7];
    const float* W3  = (const float*)d_in[8];
    const float* b3  = (const float*)d_in[9];
    float* out = (float*)d_out;

    const int nNodes = in_sizes[0] / 6;
    const int nEdges = in_sizes[1] / 2;
    const int nY     = in_sizes[2];

    cudaFuncSetAttribute(k_fused, cudaFuncAttributeMaxDynamicSharedMemorySize, SMEM_BYTES);

    k_zero<<<1, 1>>>();
    k_base<<<128, 256>>>(y, tgt, nY);
    k_prep<<<(12800 + 255) / 256, 256>>>(W1, W2, W3);
    k_fused<<<(nEdges + BM - 1) / BM, NTHR, SMEM_BYTES>>>(x, ei, b1, b2, b3, nEdges);
    k_finalize<<<1, 1>>>(out, nNodes, nEdges);
}

// round 16
// speedup vs baseline: 1.0359x; 1.0062x over previous
#include <cuda_runtime.h>
#include <cuda_bf16.h>
#include <cstdint>

// ---------------- constants ----------------
#define SH    328          // smem row stride (elems) for H1/H2 tiles (conflict-free)
#define BM    64           // edges per block
#define NTHR  320          // 10 warps
#define GRID  304          // persistent: 2 CTAs/SM x 152 SMs (GB300)
// K padded to 304 = 19 k-steps of 16 (real K = 300)

// ---------------- device scratch: weights pre-swizzled into mma fragment order ----
// uint2 fragment = 32 lanes x {b0,b1}: b0={W[k0][n],W[k0+1][n]}, b1={W[k0+8..9][n]}
// n = base_n + lane/4, k0 = base_k + (lane%4)*2   (m16n8k16.row.col B layout)
// uint4 pair = fragments for k-steps (2*ksp, 2*ksp+1): {x,y}=even step, {z,w}=odd step
__device__ uint2 g_W1f[40 * 32];       // (cg10, ni4): f = cg*4 + ni
__device__ uint4 g_W2q[400 * 32];      // (cg10, ni4, ksp10): f = cg*40 + ni*10 + ksp
__device__ uint4 g_W3q[250 * 32];      // (cg5,  ni5, ksp10): f = cg*50 + ni*10 + ksp
__device__ double g_acc[2];            // [0]=sum|y-t|, [1]=KL

__device__ __forceinline__ uint32_t smem_u32(const void* p) {
    return (uint32_t)__cvta_generic_to_shared(p);
}

__device__ __forceinline__ uint32_t pk2(const float* W, int k, int n,
                                        int K, int N, int ld) {
    float v0 = (k     < K && n < N) ? W[(size_t)k * ld + n]       : 0.f;
    float v1 = (k + 1 < K && n < N) ? W[(size_t)(k + 1) * ld + n] : 0.f;
    __nv_bfloat162 h = __floats2bfloat162_rn(v0, v1);
    return *(uint32_t*)&h;
}

__global__ void k_zero() { g_acc[0] = 0.0; g_acc[1] = 0.0; }

__global__ void k_base(const float* __restrict__ y, const float* __restrict__ tg, int n) {
    __shared__ float red[8];
    float local = 0.f;
    for (int i = blockIdx.x * blockDim.x + threadIdx.x; i < n; i += gridDim.x * blockDim.x)
        local += fabsf(y[i] - tg[i]);
    int lane = threadIdx.x & 31, warp = threadIdx.x >> 5;
    #pragma unroll
    for (int o = 16; o > 0; o >>= 1) local += __shfl_xor_sync(0xffffffffu, local, o);
    if (lane == 0) red[warp] = local;
    __syncthreads();
    if (threadIdx.x < 8) {
        float v = red[threadIdx.x];
        #pragma unroll
        for (int o = 4; o > 0; o >>= 1) v += __shfl_xor_sync(0xffu, v, o);
        if (threadIdx.x == 0) atomicAdd(&g_acc[0], (double)v);
    }
}

// ---------------- fragment prep ----------------
__global__ void k_prep(const float* __restrict__ W1,
                       const float* __restrict__ W2,
                       const float* __restrict__ W3) {
    int i = blockIdx.x * blockDim.x + threadIdx.x;
    int lane = i & 31, f = i >> 5;
    if (i < 12800) {            // W2q: [300][300], ld=300
        int cg = f / 40, r = f % 40;
        int ni = r / 10, ksp = r % 10;
        int n  = cg * 32 + ni * 8 + (lane >> 2);
        int k0 = ksp * 32 + (lane & 3) * 2;      // even step base = 2*ksp*16
        g_W2q[i] = make_uint4(pk2(W2, k0,      n, 300, 300, 300),
                              pk2(W2, k0 + 8,  n, 300, 300, 300),
                              pk2(W2, k0 + 16, n, 300, 300, 300),
                              pk2(W2, k0 + 24, n, 300, 300, 300));
    }
    if (i < 8000) {             // W3q: [300][200], ld=200
        int cg = f / 50, r = f % 50;
        int ni = r / 10, ksp = r % 10;
        int n  = cg * 40 + ni * 8 + (lane >> 2);
        int k0 = ksp * 32 + (lane & 3) * 2;
        g_W3q[i] = make_uint4(pk2(W3, k0,      n, 300, 200, 200),
                              pk2(W3, k0 + 8,  n, 300, 200, 200),
                              pk2(W3, k0 + 16, n, 300, 200, 200),
                              pk2(W3, k0 + 24, n, 300, 200, 200));
    }
    if (i < 1280) {             // W1: [12][300], ld=300, K=16 single step
        int cg = f >> 2, ni = f & 3;
        int n  = cg * 32 + ni * 8 + (lane >> 2);
        int k0 = (lane & 3) * 2;
        g_W1f[i] = make_uint2(pk2(W1, k0,     n, 12, 300, 300),
                              pk2(W1, k0 + 8, n, 12, 300, 300));
    }
}

// ---------------- smem: H1 + H2 + Es + red = ~86 KB, 2 CTAs/SM ----------------
#define ELEMS (2 * 64 * SH + 64 * 16)
#define SMEM_BYTES (ELEMS * 2 + 64)

#define MMA(acc, a, bx, by) \
    asm volatile("mma.sync.aligned.m16n8k16.row.col.f32.bf16.bf16.f32 " \
        "{%0,%1,%2,%3}, {%4,%5,%6,%7}, {%8,%9}, {%0,%1,%2,%3};\n" \
        : "+f"(acc[0]), "+f"(acc[1]), "+f"(acc[2]), "+f"(acc[3]) \
        : "r"(a[0]), "r"(a[1]), "r"(a[2]), "r"(a[3]), "r"(bx), "r"(by))

__global__ __launch_bounds__(NTHR, 2)
void k_fused(const float* __restrict__ x,
             const int*   __restrict__ ei,
             const float* __restrict__ b1,
             const float* __restrict__ b2,
             const float* __restrict__ b3,
             int nEdges, int nBlocks) {
    extern __shared__ __align__(16) char smem_raw[];
    __nv_bfloat16* base = (__nv_bfloat16*)smem_raw;
    __nv_bfloat16* H1 = base;
    __nv_bfloat16* H2 = base + 64 * SH;
    __nv_bfloat16* Es = base + 2 * 64 * SH;
    float* red = (float*)(base + ELEMS);

    const int t = threadIdx.x;
    const int lane = t & 31, warp = t >> 5;    // 10 warps
    const int mg = warp / 5;                   // m-half (stage 1/3)
    const int ig = warp % 5;                   // item group (stage 1/3)
    const int g = lane >> 2, q = lane & 3;

    // per-warp B fragment streams (loop-invariant)
    const uint2* Bf1a = g_W1f + (size_t)ig * 4 * 32 + lane;
    const uint2* Bf1b = g_W1f + (size_t)(ig + 5) * 4 * 32 + lane;
    const uint4* Bq2  = g_W2q + (size_t)warp * 40 * 32 + lane;
    const uint4* Bq3  = g_W3q + (size_t)ig * 50 * 32 + lane;

    float localKL = 0.f;   // accumulated across all tiles

    // ---- persistent tile loop ----
    #pragma unroll 1
    for (int bid = blockIdx.x; bid < nBlocks; bid += GRID) {
        const int mBase = bid * BM;

        // ---- stage 0: edge gather into Es ----
        // (the barrier below also guarantees all warps finished the previous
        //  tile's stage 3 before H1 gets overwritten in stage 1)
        if (t < 128) {
            int el = t >> 1, half = t & 1;
            int e = mBase + el;
            __nv_bfloat16* row = Es + el * 16 + half * 6;
            float v[6] = {0.f, 0.f, 0.f, 0.f, 0.f, 0.f};
            if (e < nEdges) {
                int node = ei[half ? (size_t)nEdges + e : (size_t)e];
                const float* xp = x + (size_t)node * 6;
                float2 a0 = *(const float2*)xp;
                float2 a1 = *(const float2*)(xp + 2);
                float2 a2 = *(const float2*)(xp + 4);
                v[0] = a0.x; v[1] = a0.y; v[2] = a1.x; v[3] = a1.y; v[4] = a2.x; v[5] = a2.y;
            }
            #pragma unroll
            for (int k = 0; k < 6; k++) row[k] = __float2bfloat16(v[k]);
            if (half) {
                *(__nv_bfloat162*)(Es + el * 16 + 12) = __floats2bfloat162_rn(0.f, 0.f);
                *(__nv_bfloat162*)(Es + el * 16 + 14) = __floats2bfloat162_rn(0.f, 0.f);
            }
        }
        __syncthreads();

        // ---- stage 1: GEMM1 (Es @ W1) -> H1 ; items cg = ig, ig+5 ----
        {
            float acc[2][4][4];
            uint32_t a[2][4];
            const int arow = mg * 32 + (lane & 15);
            const int acol = (lane >> 4) * 8;
            #pragma unroll
            for (int mi = 0; mi < 2; mi++)
                asm volatile("ldmatrix.sync.aligned.m8n8.x4.shared.b16 {%0,%1,%2,%3}, [%4];\n"
                    : "=r"(a[mi][0]), "=r"(a[mi][1]), "=r"(a[mi][2]), "=r"(a[mi][3])
                    : "r"(smem_u32(Es + (arow + mi * 16) * 16 + acol)));
            #pragma unroll
            for (int it = 0; it < 2; it++) {
                const int cg = ig + it * 5;
                const uint2* Bf = it ? Bf1b : Bf1a;
                #pragma unroll
                for (int mi = 0; mi < 2; mi++)
                    #pragma unroll
                    for (int ni = 0; ni < 4; ni++)
                        #pragma unroll
                        for (int r = 0; r < 4; r++) acc[mi][ni][r] = 0.f;
                #pragma unroll
                for (int ni = 0; ni < 4; ni++) {
                    uint2 bv = __ldg(Bf + ni * 32);
                    #pragma unroll
                    for (int mi = 0; mi < 2; mi++) MMA(acc[mi][ni], a[mi], bv.x, bv.y);
                }
                #pragma unroll
                for (int mi = 0; mi < 2; mi++)
                    #pragma unroll
                    for (int ni = 0; ni < 4; ni++) {
                        int c0 = cg * 32 + ni * 8 + q * 2;
                        float bb0 = (c0 < 300)     ? __ldg(b1 + c0)     : 0.f;
                        float bb1 = (c0 + 1 < 300) ? __ldg(b1 + c0 + 1) : 0.f;
                        int r0 = mg * 32 + mi * 16 + g;
                        *(__nv_bfloat162*)(H1 + r0 * SH + c0) = __floats2bfloat162_rn(
                            fmaxf(acc[mi][ni][0] + bb0, 0.f), fmaxf(acc[mi][ni][1] + bb1, 0.f));
                        *(__nv_bfloat162*)(H1 + (r0 + 8) * SH + c0) = __floats2bfloat162_rn(
                            fmaxf(acc[mi][ni][2] + bb0, 0.f), fmaxf(acc[mi][ni][3] + bb1, 0.f));
                    }
            }
        }
        __syncthreads();   // H1 published

        // ---- stage 2: GEMM2 (H1 @ W2) -> H2 ; one item/warp, mi=4, NI=4, K=304 ----
        {
            float acc[4][4][4];
            #pragma unroll
            for (int mi = 0; mi < 4; mi++)
                #pragma unroll
                for (int ni = 0; ni < 4; ni++)
                    #pragma unroll
                    for (int r = 0; r < 4; r++) acc[mi][ni][r] = 0.f;
            const uint32_t aBase1 = smem_u32(H1 + (lane & 15) * SH) + ((lane >> 4) * 8) * 2;
            #pragma unroll
            for (int ksp = 0; ksp < 10; ksp++) {
                uint4 bq[4];
                #pragma unroll
                for (int ni = 0; ni < 4; ni++)
                    bq[ni] = __ldg(Bq2 + (ni * 10 + ksp) * 32);
                {   // even k-step (2*ksp)
                    uint32_t a[4][4];
                    const uint32_t ac = aBase1 + (ksp * 32) * 2;
                    #pragma unroll
                    for (int mi = 0; mi < 4; mi++)
                        asm volatile("ldmatrix.sync.aligned.m8n8.x4.shared.b16 {%0,%1,%2,%3}, [%4];\n"
                            : "=r"(a[mi][0]), "=r"(a[mi][1]), "=r"(a[mi][2]), "=r"(a[mi][3])
                            : "r"(ac + mi * 16 * SH * 2));
                    #pragma unroll
                    for (int mi = 0; mi < 4; mi++)
                        #pragma unroll
                        for (int ni = 0; ni < 4; ni++)
                            MMA(acc[mi][ni], a[mi], bq[ni].x, bq[ni].y);
                }
                if (ksp < 9) {   // odd k-step; step 19 doesn't exist (K=304)
                    uint32_t a[4][4];
                    const uint32_t ac = aBase1 + (ksp * 32 + 16) * 2;
                    #pragma unroll
                    for (int mi = 0; mi < 4; mi++)
                        asm volatile("ldmatrix.sync.aligned.m8n8.x4.shared.b16 {%0,%1,%2,%3}, [%4];\n"
                            : "=r"(a[mi][0]), "=r"(a[mi][1]), "=r"(a[mi][2]), "=r"(a[mi][3])
                            : "r"(ac + mi * 16 * SH * 2));
                    #pragma unroll
                    for (int mi = 0; mi < 4; mi++)
                        #pragma unroll
                        for (int ni = 0; ni < 4; ni++)
                            MMA(acc[mi][ni], a[mi], bq[ni].z, bq[ni].w);
                }
            }
            #pragma unroll
            for (int mi = 0; mi < 4; mi++)
                #pragma unroll
                for (int ni = 0; ni < 4; ni++) {
                    int c0 = warp * 32 + ni * 8 + q * 2;
                    float bb0 = (c0 < 300)     ? __ldg(b2 + c0)     : 0.f;
                    float bb1 = (c0 + 1 < 300) ? __ldg(b2 + c0 + 1) : 0.f;
                    int r0 = mi * 16 + g;
                    *(__nv_bfloat162*)(H2 + r0 * SH + c0) = __floats2bfloat162_rn(
                        fmaxf(acc[mi][ni][0] + bb0, 0.f), fmaxf(acc[mi][ni][1] + bb1, 0.f));
                    *(__nv_bfloat162*)(H2 + (r0 + 8) * SH + c0) = __floats2bfloat162_rn(
                        fmaxf(acc[mi][ni][2] + bb0, 0.f), fmaxf(acc[mi][ni][3] + bb1, 0.f));
                }
        }
        __syncthreads();   // H2 published

        // ---- stage 3: GEMM3 (H2 @ W3), 2mg x 5ig, NI=5, K=304, fused KL ----
        {
            float acc[2][5][4];
            #pragma unroll
            for (int mi = 0; mi < 2; mi++)
                #pragma unroll
                for (int ni = 0; ni < 5; ni++)
                    #pragma unroll
                    for (int r = 0; r < 4; r++) acc[mi][ni][r] = 0.f;
            const uint32_t aBase2 = smem_u32(H2 + (mg * 32 + (lane & 15)) * SH)
                                  + ((lane >> 4) * 8) * 2;
            #pragma unroll
            for (int ksp = 0; ksp < 10; ksp++) {
                uint4 bq[5];
                #pragma unroll
                for (int ni = 0; ni < 5; ni++)
                    bq[ni] = __ldg(Bq3 + (ni * 10 + ksp) * 32);
                {
                    uint32_t a[2][4];
                    const uint32_t ac = aBase2 + (ksp * 32) * 2;
                    #pragma unroll
                    for (int mi = 0; mi < 2; mi++)
                        asm volatile("ldmatrix.sync.aligned.m8n8.x4.shared.b16 {%0,%1,%2,%3}, [%4];\n"
                            : "=r"(a[mi][0]), "=r"(a[mi][1]), "=r"(a[mi][2]), "=r"(a[mi][3])
                            : "r"(ac + mi * 16 * SH * 2));
                    #pragma unroll
                    for (int mi = 0; mi < 2; mi++)
                        #pragma unroll
                        for (int ni = 0; ni < 5; ni++)
                            MMA(acc[mi][ni], a[mi], bq[ni].x, bq[ni].y);
                }
                if (ksp < 9) {
                    uint32_t a[2][4];
                    const uint32_t ac = aBase2 + (ksp * 32 + 16) * 2;
                    #pragma unroll
                    for (int mi = 0; mi < 2; mi++)
                        asm volatile("ldmatrix.sync.aligned.m8n8.x4.shared.b16 {%0,%1,%2,%3}, [%4];\n"
                            : "=r"(a[mi][0]), "=r"(a[mi][1]), "=r"(a[mi][2]), "=r"(a[mi][3])
                            : "r"(ac + mi * 16 * SH * 2));
                    #pragma unroll
                    for (int mi = 0; mi < 2; mi++)
                        #pragma unroll
                        for (int ni = 0; ni < 5; ni++)
                            MMA(acc[mi][ni], a[mi], bq[ni].z, bq[ni].w);
                }
            }
            #pragma unroll
            for (int mi = 0; mi < 2; mi++)
                #pragma unroll
                for (int ni = 0; ni < 5; ni++) {
                    int c0 = ig * 40 + ni * 8 + q * 2;       // 0..199
                    int r0 = mBase + mg * 32 + mi * 16 + g;
                    float bb0 = __ldg(b3 + c0), bb1 = __ldg(b3 + c0 + 1);
                    #pragma unroll
                    for (int h = 0; h < 2; h++) {
                        if (r0 + h * 8 >= nEdges) continue;
                        float v0 = acc[mi][ni][h * 2]     + bb0;
                        float v1 = acc[mi][ni][h * 2 + 1] + bb1;
                        localKL += (c0 < 100) ? 0.5f * (v0 * v0 + v1 * v1)
                                              : 0.5f * ((__expf(v0) - v0 - 1.f)
                                                      + (__expf(v1) - v1 - 1.f));
                    }
                }
        }
        // no trailing barrier: next iteration's Es-sync orders stage-3 reads
        // before H1/H2 overwrites (Es region is disjoint from H1/H2).
    }

    // ---- block reduce + single atomic ----
    #pragma unroll
    for (int o = 16; o > 0; o >>= 1) localKL += __shfl_xor_sync(0xffffffffu, localKL, o);
    if (lane == 0) red[warp] = localKL;
    __syncthreads();
    if (t == 0) {
        float s = 0.f;
        #pragma unroll
        for (int w = 0; w < 10; w++) s += red[w];
        atomicAdd(&g_acc[1], (double)s);
    }
}

__global__ void k_finalize(float* out, int nNodes, int nEdges) {
    out[0] = (float)(g_acc[0] / (double)nNodes + g_acc[1] / (double)nEdges);
}

extern "C" void kernel_launch(void* const* d_in, const int* in_sizes, int n_in,
                              void* d_out, int out_size) {
    const float* x   = (const float*)d_in[0];
    const int*   ei  = (const int*)  d_in[1];
    const float* y   = (const float*)d_in[2];
    const float* tgt = (const float*)d_in[3];
    const float* W1  = (const float*)d_in[4];
    const float* b1  = (const float*)d_in[5];
    const float* W2  = (const float*)d_in[6];
    const float* b2  = (const float*)d_in[7];
    const float* W3  = (const float*)d_in[8];
    const float* b3  = (const float*)d_in[9];
    float* out = (float*)d_out;

    const int nNodes  = in_sizes[0] / 6;
    const int nEdges  = in_sizes[1] / 2;
    const int nY      = in_sizes[2];
    const int nBlocks = (nEdges + BM - 1) / BM;

    cudaFuncSetAttribute(k_fused, cudaFuncAttributeMaxDynamicSharedMemorySize, SMEM_BYTES);

    k_zero<<<1, 1>>>();
    k_base<<<128, 256>>>(y, tgt, nY);
    k_prep<<<(12800 + 255) / 256, 256>>>(W1, W2, W3);
    k_fused<<<GRID, NTHR, SMEM_BYTES>>>(x, ei, b1, b2, b3, nEdges, nBlocks);
    k_finalize<<<1, 1>>>(out, nNodes, nEdges);
}

// round 17
// speedup vs baseline: 1.1410x; 1.1015x over previous
#include <cuda_runtime.h>
#include <cuda_bf16.h>
#include <cstdint>

// ---------------- constants ----------------
#define SH    328          // smem row stride (elems) for H1/H2 tiles (conflict-free)
#define BM    64           // edges per block
#define NTHR  320          // 10 warps
// K padded to 304 = 19 k-steps of 16 (real K = 300)

// ---------------- device scratch: weights pre-swizzled into mma fragment order ----
// uint2 fragment = 32 lanes x {b0,b1}: b0={W[k0][n],W[k0+1][n]}, b1={W[k0+8..9][n]}
// n = base_n + lane/4, k0 = base_k + (lane%4)*2   (m16n8k16.row.col B layout)
// uint4 pair = fragments for k-steps (2*ksp, 2*ksp+1): {x,y}=even step, {z,w}=odd step
__device__ uint2 g_W1f[40 * 32];       // (cg10, ni4): f = cg*4 + ni
__device__ uint4 g_W2q[400 * 32];      // (cg10, ni4, ksp10): f = cg*40 + ni*10 + ksp
__device__ uint4 g_W3q[250 * 32];      // (cg5,  ni5, ksp10): f = cg*50 + ni*10 + ksp
__device__ double g_acc[2];            // [0]=sum|y-t|, [1]=KL

__device__ __forceinline__ uint32_t smem_u32(const void* p) {
    return (uint32_t)__cvta_generic_to_shared(p);
}

__device__ __forceinline__ uint32_t pk2(const float* W, int k, int n,
                                        int K, int N, int ld) {
    float v0 = (k     < K && n < N) ? W[(size_t)k * ld + n]       : 0.f;
    float v1 = (k + 1 < K && n < N) ? W[(size_t)(k + 1) * ld + n] : 0.f;
    __nv_bfloat162 h = __floats2bfloat162_rn(v0, v1);
    return *(uint32_t*)&h;
}

__global__ void k_base(const float* __restrict__ y, const float* __restrict__ tg, int n) {
    __shared__ float red[8];
    float local = 0.f;
    for (int i = blockIdx.x * blockDim.x + threadIdx.x; i < n; i += gridDim.x * blockDim.x)
        local += fabsf(y[i] - tg[i]);
    int lane = threadIdx.x & 31, warp = threadIdx.x >> 5;
    #pragma unroll
    for (int o = 16; o > 0; o >>= 1) local += __shfl_xor_sync(0xffffffffu, local, o);
    if (lane == 0) red[warp] = local;
    __syncthreads();
    if (threadIdx.x < 8) {
        float v = red[threadIdx.x];
        #pragma unroll
        for (int o = 4; o > 0; o >>= 1) v += __shfl_xor_sync(0xffu, v, o);
        if (threadIdx.x == 0) atomicAdd(&g_acc[0], (double)v);
    }
}

// ---------------- fragment prep (also zeroes accumulators; runs before k_base) ----
__global__ void k_prep(const float* __restrict__ W1,
                       const float* __restrict__ W2,
                       const float* __restrict__ W3) {
    int i = blockIdx.x * blockDim.x + threadIdx.x;
    if (i == 0) { g_acc[0] = 0.0; g_acc[1] = 0.0; }
    int lane = i & 31, f = i >> 5;
    if (i < 12800) {            // W2q: [300][300], ld=300
        int cg = f / 40, r = f % 40;
        int ni = r / 10, ksp = r % 10;
        int n  = cg * 32 + ni * 8 + (lane >> 2);
        int k0 = ksp * 32 + (lane & 3) * 2;      // even step base = 2*ksp*16
        g_W2q[i] = make_uint4(pk2(W2, k0,      n, 300, 300, 300),
                              pk2(W2, k0 + 8,  n, 300, 300, 300),
                              pk2(W2, k0 + 16, n, 300, 300, 300),
                              pk2(W2, k0 + 24, n, 300, 300, 300));
    }
    if (i < 8000) {             // W3q: [300][200], ld=200
        int cg = f / 50, r = f % 50;
        int ni = r / 10, ksp = r % 10;
        int n  = cg * 40 + ni * 8 + (lane >> 2);
        int k0 = ksp * 32 + (lane & 3) * 2;
        g_W3q[i] = make_uint4(pk2(W3, k0,      n, 300, 200, 200),
                              pk2(W3, k0 + 8,  n, 300, 200, 200),
                              pk2(W3, k0 + 16, n, 300, 200, 200),
                              pk2(W3, k0 + 24, n, 300, 200, 200));
    }
    if (i < 1280) {             // W1: [12][300], ld=300, K=16 single step
        int cg = f >> 2, ni = f & 3;
        int n  = cg * 32 + ni * 8 + (lane >> 2);
        int k0 = (lane & 3) * 2;
        g_W1f[i] = make_uint2(pk2(W1, k0,     n, 12, 300, 300),
                              pk2(W1, k0 + 8, n, 12, 300, 300));
    }
}

// ---------------- smem: H1 + H2 + Es + red = ~86 KB, 2 CTAs/SM ----------------
#define ELEMS (2 * 64 * SH + 64 * 16)
#define SMEM_BYTES (ELEMS * 2 + 64)

#define MMA(acc, a, bx, by) \
    asm volatile("mma.sync.aligned.m16n8k16.row.col.f32.bf16.bf16.f32 " \
        "{%0,%1,%2,%3}, {%4,%5,%6,%7}, {%8,%9}, {%0,%1,%2,%3};\n" \
        : "+f"(acc[0]), "+f"(acc[1]), "+f"(acc[2]), "+f"(acc[3]) \
        : "r"(a[0]), "r"(a[1]), "r"(a[2]), "r"(a[3]), "r"(bx), "r"(by))

__global__ __launch_bounds__(NTHR, 2)
void k_fused(const float* __restrict__ x,
             const int*   __restrict__ ei,
             const float* __restrict__ b1,
             const float* __restrict__ b2,
             const float* __restrict__ b3,
             int nEdges) {
    extern __shared__ __align__(16) char smem_raw[];
    __nv_bfloat16* base = (__nv_bfloat16*)smem_raw;
    __nv_bfloat16* H1 = base;
    __nv_bfloat16* H2 = base + 64 * SH;
    __nv_bfloat16* Es = base + 2 * 64 * SH;
    float* red = (float*)(base + ELEMS);

    const int t = threadIdx.x;
    const int lane = t & 31, warp = t >> 5;    // 10 warps
    const int mg = warp / 5;                   // m-half (stage 1/3)
    const int ig = warp % 5;                   // item group (stage 1/3)
    const int mBase = blockIdx.x * BM;
    const int g = lane >> 2, q = lane & 3;

    // ---- stage 0: edge gather into Es ----
    if (t < 128) {
        int el = t >> 1, half = t & 1;
        int e = mBase + el;
        __nv_bfloat16* row = Es + el * 16 + half * 6;
        float v[6] = {0.f, 0.f, 0.f, 0.f, 0.f, 0.f};
        if (e < nEdges) {
            int node = ei[half ? (size_t)nEdges + e : (size_t)e];
            const float* xp = x + (size_t)node * 6;
            float2 a0 = *(const float2*)xp;
            float2 a1 = *(const float2*)(xp + 2);
            float2 a2 = *(const float2*)(xp + 4);
            v[0] = a0.x; v[1] = a0.y; v[2] = a1.x; v[3] = a1.y; v[4] = a2.x; v[5] = a2.y;
        }
        #pragma unroll
        for (int k = 0; k < 6; k++) row[k] = __float2bfloat16(v[k]);
        if (half) {
            *(__nv_bfloat162*)(Es + el * 16 + 12) = __floats2bfloat162_rn(0.f, 0.f);
            *(__nv_bfloat162*)(Es + el * 16 + 14) = __floats2bfloat162_rn(0.f, 0.f);
        }
    }
    __syncthreads();

    // ---- stage 1: GEMM1 (Es @ W1) -> H1 ; 2mg x 5ig, items cg = ig, ig+5 ----
    {
        float acc[2][4][4];
        uint32_t a[2][4];
        const int arow = mg * 32 + (lane & 15);
        const int acol = (lane >> 4) * 8;
        #pragma unroll
        for (int mi = 0; mi < 2; mi++)
            asm volatile("ldmatrix.sync.aligned.m8n8.x4.shared.b16 {%0,%1,%2,%3}, [%4];\n"
                : "=r"(a[mi][0]), "=r"(a[mi][1]), "=r"(a[mi][2]), "=r"(a[mi][3])
                : "r"(smem_u32(Es + (arow + mi * 16) * 16 + acol)));
        #pragma unroll
        for (int it = 0; it < 2; it++) {
            const int cg = ig + it * 5;
            #pragma unroll
            for (int mi = 0; mi < 2; mi++)
                #pragma unroll
                for (int ni = 0; ni < 4; ni++)
                    #pragma unroll
                    for (int r = 0; r < 4; r++) acc[mi][ni][r] = 0.f;
            const uint2* Bf = g_W1f + (size_t)cg * 4 * 32 + lane;
            #pragma unroll
            for (int ni = 0; ni < 4; ni++) {
                uint2 bv = __ldg(Bf + ni * 32);
                #pragma unroll
                for (int mi = 0; mi < 2; mi++) MMA(acc[mi][ni], a[mi], bv.x, bv.y);
            }
            #pragma unroll
            for (int mi = 0; mi < 2; mi++)
                #pragma unroll
                for (int ni = 0; ni < 4; ni++) {
                    int c0 = cg * 32 + ni * 8 + q * 2;
                    float bb0 = (c0 < 300)     ? __ldg(b1 + c0)     : 0.f;
                    float bb1 = (c0 + 1 < 300) ? __ldg(b1 + c0 + 1) : 0.f;
                    int r0 = mg * 32 + mi * 16 + g;
                    *(__nv_bfloat162*)(H1 + r0 * SH + c0) = __floats2bfloat162_rn(
                        fmaxf(acc[mi][ni][0] + bb0, 0.f), fmaxf(acc[mi][ni][1] + bb1, 0.f));
                    *(__nv_bfloat162*)(H1 + (r0 + 8) * SH + c0) = __floats2bfloat162_rn(
                        fmaxf(acc[mi][ni][2] + bb0, 0.f), fmaxf(acc[mi][ni][3] + bb1, 0.f));
                }
        }
    }
    __syncthreads();   // H1 published

    // ---- stage 2: GEMM2 (H1 @ W2) -> H2 ; one item/warp, mi=4, NI=4, K=304 ----
    {
        float acc[4][4][4];
        const int cg = warp;
        #pragma unroll
        for (int mi = 0; mi < 4; mi++)
            #pragma unroll
            for (int ni = 0; ni < 4; ni++)
                #pragma unroll
                for (int r = 0; r < 4; r++) acc[mi][ni][r] = 0.f;
        const uint32_t aBase1 = smem_u32(H1 + (lane & 15) * SH) + ((lane >> 4) * 8) * 2;
        const uint4* Bq = g_W2q + (size_t)cg * 40 * 32 + lane;
        #pragma unroll
        for (int ksp = 0; ksp < 10; ksp++) {
            uint4 bq[4];
            #pragma unroll
            for (int ni = 0; ni < 4; ni++)
                bq[ni] = __ldg(Bq + (ni * 10 + ksp) * 32);
            {   // even k-step (2*ksp)
                uint32_t a[4][4];
                const uint32_t ac = aBase1 + (ksp * 32) * 2;
                #pragma unroll
                for (int mi = 0; mi < 4; mi++)
                    asm volatile("ldmatrix.sync.aligned.m8n8.x4.shared.b16 {%0,%1,%2,%3}, [%4];\n"
                        : "=r"(a[mi][0]), "=r"(a[mi][1]), "=r"(a[mi][2]), "=r"(a[mi][3])
                        : "r"(ac + mi * 16 * SH * 2));
                #pragma unroll
                for (int mi = 0; mi < 4; mi++)
                    #pragma unroll
                    for (int ni = 0; ni < 4; ni++)
                        MMA(acc[mi][ni], a[mi], bq[ni].x, bq[ni].y);
            }
            if (ksp < 9) {   // odd k-step (2*ksp+1); step 19 doesn't exist (K=304)
                uint32_t a[4][4];
                const uint32_t ac = aBase1 + (ksp * 32 + 16) * 2;
                #pragma unroll
                for (int mi = 0; mi < 4; mi++)
                    asm volatile("ldmatrix.sync.aligned.m8n8.x4.shared.b16 {%0,%1,%2,%3}, [%4];\n"
                        : "=r"(a[mi][0]), "=r"(a[mi][1]), "=r"(a[mi][2]), "=r"(a[mi][3])
                        : "r"(ac + mi * 16 * SH * 2));
                #pragma unroll
                for (int mi = 0; mi < 4; mi++)
                    #pragma unroll
                    for (int ni = 0; ni < 4; ni++)
                        MMA(acc[mi][ni], a[mi], bq[ni].z, bq[ni].w);
            }
        }
        #pragma unroll
        for (int mi = 0; mi < 4; mi++)
            #pragma unroll
            for (int ni = 0; ni < 4; ni++) {
                int c0 = cg * 32 + ni * 8 + q * 2;
                float bb0 = (c0 < 300)     ? __ldg(b2 + c0)     : 0.f;
                float bb1 = (c0 + 1 < 300) ? __ldg(b2 + c0 + 1) : 0.f;
                int r0 = mi * 16 + g;
                *(__nv_bfloat162*)(H2 + r0 * SH + c0) = __floats2bfloat162_rn(
                    fmaxf(acc[mi][ni][0] + bb0, 0.f), fmaxf(acc[mi][ni][1] + bb1, 0.f));
                *(__nv_bfloat162*)(H2 + (r0 + 8) * SH + c0) = __floats2bfloat162_rn(
                    fmaxf(acc[mi][ni][2] + bb0, 0.f), fmaxf(acc[mi][ni][3] + bb1, 0.f));
            }
    }
    __syncthreads();   // H2 published

    // ---- stage 3: GEMM3 (H2 @ W3), 2mg x 5ig, NI=5, K=304, fused KL ----
    float localKL = 0.f;
    {
        float acc[2][5][4];
        const int cg = ig;
        #pragma unroll
        for (int mi = 0; mi < 2; mi++)
            #pragma unroll
            for (int ni = 0; ni < 5; ni++)
                #pragma unroll
                for (int r = 0; r < 4; r++) acc[mi][ni][r] = 0.f;
        const uint32_t aBase2 = smem_u32(H2 + (mg * 32 + (lane & 15)) * SH) + ((lane >> 4) * 8) * 2;
        const uint4* Bq = g_W3q + (size_t)cg * 50 * 32 + lane;
        #pragma unroll
        for (int ksp = 0; ksp < 10; ksp++) {
            uint4 bq[5];
            #pragma unroll
            for (int ni = 0; ni < 5; ni++)
                bq[ni] = __ldg(Bq + (ni * 10 + ksp) * 32);
            {
                uint32_t a[2][4];
                const uint32_t ac = aBase2 + (ksp * 32) * 2;
                #pragma unroll
                for (int mi = 0; mi < 2; mi++)
                    asm volatile("ldmatrix.sync.aligned.m8n8.x4.shared.b16 {%0,%1,%2,%3}, [%4];\n"
                        : "=r"(a[mi][0]), "=r"(a[mi][1]), "=r"(a[mi][2]), "=r"(a[mi][3])
                        : "r"(ac + mi * 16 * SH * 2));
                #pragma unroll
                for (int mi = 0; mi < 2; mi++)
                    #pragma unroll
                    for (int ni = 0; ni < 5; ni++)
                        MMA(acc[mi][ni], a[mi], bq[ni].x, bq[ni].y);
            }
            if (ksp < 9) {
                uint32_t a[2][4];
                const uint32_t ac = aBase2 + (ksp * 32 + 16) * 2;
                #pragma unroll
                for (int mi = 0; mi < 2; mi++)
                    asm volatile("ldmatrix.sync.aligned.m8n8.x4.shared.b16 {%0,%1,%2,%3}, [%4];\n"
                        : "=r"(a[mi][0]), "=r"(a[mi][1]), "=r"(a[mi][2]), "=r"(a[mi][3])
                        : "r"(ac + mi * 16 * SH * 2));
                #pragma unroll
                for (int mi = 0; mi < 2; mi++)
                    #pragma unroll
                    for (int ni = 0; ni < 5; ni++)
                        MMA(acc[mi][ni], a[mi], bq[ni].z, bq[ni].w);
            }
        }
        #pragma unroll
        for (int mi = 0; mi < 2; mi++)
            #pragma unroll
            for (int ni = 0; ni < 5; ni++) {
                int c0 = cg * 40 + ni * 8 + q * 2;       // 0..199, no col guard needed
                int r0 = mBase + mg * 32 + mi * 16 + g;
                float bb0 = __ldg(b3 + c0), bb1 = __ldg(b3 + c0 + 1);
                #pragma unroll
                for (int h = 0; h < 2; h++) {
                    if (r0 + h * 8 >= nEdges) continue;
                    float v0 = acc[mi][ni][h * 2]     + bb0;
                    float v1 = acc[mi][ni][h * 2 + 1] + bb1;
                    localKL += (c0 < 100) ? 0.5f * (v0 * v0 + v1 * v1)
                                          : 0.5f * ((__expf(v0) - v0 - 1.f)
                                                  + (__expf(v1) - v1 - 1.f));
                }
            }
    }

    // ---- block reduce + atomic ----
    #pragma unroll
    for (int o = 16; o > 0; o >>= 1) localKL += __shfl_xor_sync(0xffffffffu, localKL, o);
    if (lane == 0) red[warp] = localKL;
    __syncthreads();
    if (t == 0) {
        float s = 0.f;
        #pragma unroll
        for (int w = 0; w < 10; w++) s += red[w];
        atomicAdd(&g_acc[1], (double)s);
    }
}

__global__ void k_finalize(float* out, int nNodes, int nEdges) {
    out[0] = (float)(g_acc[0] / (double)nNodes + g_acc[1] / (double)nEdges);
}

extern "C" void kernel_launch(void* const* d_in, const int* in_sizes, int n_in,
                              void* d_out, int out_size) {
    const float* x   = (const float*)d_in[0];
    const int*   ei  = (const int*)  d_in[1];
    const float* y   = (const float*)d_in[2];
    const float* tgt = (const float*)d_in[3];
    const float* W1  = (const float*)d_in[4];
    const float* b1  = (const float*)d_in[5];
    const float* W2  = (const float*)d_in[6];
    const float* b2  = (const float*)d_in[7];
    const float* W3  = (const float*)d_in[8];
    const float* b3  = (const float*)d_in[9];
    float* out = (float*)d_out;

    const int nNodes = in_sizes[0] / 6;
    const int nEdges = in_sizes[1] / 2;
    const int nY     = in_sizes[2];

    cudaFuncSetAttribute(k_fused, cudaFuncAttributeMaxDynamicSharedMemorySize, SMEM_BYTES);

    k_prep<<<(12800 + 255) / 256, 256>>>(W1, W2, W3);   // also zeroes g_acc
    k_base<<<128, 256>>>(y, tgt, nY);
    k_fused<<<(nEdges + BM - 1) / BM, NTHR, SMEM_BYTES>>>(x, ei, b1, b2, b3, nEdges);
    k_finalize<<<1, 1>>>(out, nNodes, nEdges);
}